// round 4
// baseline (speedup 1.0000x reference)
#include <cuda_runtime.h>
#include <math.h>

typedef unsigned long long u64;

#define BB 8
#define SS 2048
#define DIN 128
#define DD 40
#define DP 20
#define NROWS (BB*SS)
#define RSPLIT 8
#define KEYS_PER (SS/RSPLIT)   // 256
#define TKA 64                 // keys per smem tile in attn

// ---------- scratch ----------
__device__ float g_x[NROWS*DD];
__device__ float g_q[NROWS*DD];
__device__ float g_k[NROWS*DD];
__device__ float g_v[NROWS*DD];
__device__ float g_pm[RSPLIT*NROWS];
__device__ float g_pl[RSPLIT*NROWS];
__device__ float g_po[(size_t)RSPLIT*NROWS*DD];

// ---------- f32x2 helpers ----------
__device__ __forceinline__ u64 pack2(float x, float y) {
    u64 r; asm("mov.b64 %0,{%1,%2};" : "=l"(r) : "f"(x), "f"(y)); return r;
}
__device__ __forceinline__ float2 unpack2(u64 a) {
    float x, y; asm("mov.b64 {%0,%1},%2;" : "=f"(x), "=f"(y) : "l"(a));
    return make_float2(x, y);
}
__device__ __forceinline__ u64 ffma2(u64 a, u64 b, u64 c) {
    u64 d; asm("fma.rn.f32x2 %0,%1,%2,%3;" : "=l"(d) : "l"(a), "l"(b), "l"(c)); return d;
}
__device__ __forceinline__ u64 fmul2(u64 a, u64 b) {
    u64 d; asm("mul.rn.f32x2 %0,%1,%2;" : "=l"(d) : "l"(a), "l"(b)); return d;
}
__device__ __forceinline__ u64 fadd2(u64 a, u64 b) {
    u64 d; asm("add.rn.f32x2 %0,%1,%2;" : "=l"(d) : "l"(a), "l"(b)); return d;
}
__device__ __forceinline__ void lds2(u64& a, u64& b, unsigned addr) {
    asm("ld.shared.v2.b64 {%0,%1},[%2];" : "=l"(a), "=l"(b) : "r"(addr));
}
__device__ __forceinline__ u64 lds1(unsigned addr) {
    u64 a; asm("ld.shared.b64 %0,[%1];" : "=l"(a) : "r"(addr)); return a;
}

// bucket mapping, f32 op order matches jax reference
__device__ __forceinline__ int rel_bucket(int rel) {
    int bucket = (rel > 0) ? 16 : 0;
    int a = rel < 0 ? -rel : rel;
    if (a < 8) return bucket + a;
    float v = (logf((float)a * 0.125f) / 2.7725887222397811f) * 8.0f;
    int large = 8 + (int)v;
    return bucket + ((large < 15) ? large : 15);
}

// ---------- kernel A: 4 threads per row (k-split adapter), 256 thr/CTA ----------
// row = blockIdx.x*64 + (tid>>2); sub = tid&3 owns k-range [sub*32, sub*32+32)
// and output cols [sub*10, sub*10+10) for Q/K/V.
__global__ __launch_bounds__(256, 2) void kernelA(
    const float* __restrict__ embs, const float* __restrict__ Wa,
    const float* __restrict__ ba,   const float* __restrict__ ln1,
    const float* __restrict__ Wq,   const float* __restrict__ Wk,
    const float* __restrict__ Wv)
{
    __shared__ __align__(16) float Wa_s[DIN*DD];
    __shared__ __align__(16) float Wq_s[DD*DD], Wk_s[DD*DD], Wv_s[DD*DD];
    __shared__ __align__(16) float ba_s[DD], ln1_s[DD];

    int tid = threadIdx.x;
    for (int i = tid; i < DIN*DD/4; i += 256) ((float4*)Wa_s)[i] = ((const float4*)Wa)[i];
    for (int i = tid; i < DD*DD/4; i += 256) {
        ((float4*)Wq_s)[i] = ((const float4*)Wq)[i];
        ((float4*)Wk_s)[i] = ((const float4*)Wk)[i];
        ((float4*)Wv_s)[i] = ((const float4*)Wv)[i];
    }
    if (tid < DD) { ba_s[tid] = ba[tid]; ln1_s[tid] = ln1[tid]; }
    __syncthreads();

    int sub = tid & 3;
    size_t row = (size_t)blockIdx.x * 64 + (tid >> 2);
    unsigned wa = (unsigned)__cvta_generic_to_shared(Wa_s);

    // ---- adapter partial: k in [sub*32, sub*32+32) ----
    u64 acc[DP];
    #pragma unroll
    for (int p = 0; p < DP; p++) acc[p] = 0ull;

    const float4* erow = (const float4*)(embs + row * DIN) + sub * 8;
    #pragma unroll 2
    for (int c = 0; c < 8; c++) {
        float4 e = erow[c];
        float ej[4] = {e.x, e.y, e.z, e.w};
        #pragma unroll
        for (int j = 0; j < 4; j++) {
            u64 ee = pack2(ej[j], ej[j]);
            unsigned base = wa + (sub*32 + 4*c + j) * (DD*4);
            #pragma unroll
            for (int p = 0; p < 10; p++) {
                u64 ua, ub;
                lds2(ua, ub, base + p * 16);
                acc[2*p]   = ffma2(ee, ua, acc[2*p]);
                acc[2*p+1] = ffma2(ee, ub, acc[2*p+1]);
            }
        }
    }

    // ---- quad butterfly reduce (subs 0..3 are consecutive lanes) ----
    float xa[DD];
    #pragma unroll
    for (int p = 0; p < DP; p++) {
        float2 f = unpack2(acc[p]);
        xa[2*p] = f.x; xa[2*p+1] = f.y;
    }
    #pragma unroll
    for (int k = 0; k < DD; k++) {
        xa[k] += __shfl_xor_sync(0xffffffffu, xa[k], 1);
        xa[k] += __shfl_xor_sync(0xffffffffu, xa[k], 2);
    }

    // relu + bias, store x, rms
    float ssq = 0.f;
    #pragma unroll
    for (int k = 0; k < DD; k++) {
        float v = fmaxf(xa[k] + ba_s[k], 0.f);
        xa[k] = v;
        ssq += v * v;
    }
    {   // each sub stores its 10-float quarter of x (contiguous across quad)
        float* xp = g_x + row * DD + sub * 10;
        #pragma unroll
        for (int j = 0; j < 5; j++)
            *(float2*)(xp + 2*j) = make_float2(xa[sub*10 + 2*j], xa[sub*10 + 2*j + 1]);
    }
    float rinv = rsqrtf(ssq / 40.0f + 1e-6f);
    #pragma unroll
    for (int k = 0; k < DD; k++) xa[k] = xa[k] * rinv * ln1_s[k];

    // ---- QKV: each thread computes cols [sub*10, sub*10+10) of q,k,v ----
    unsigned wq = (unsigned)__cvta_generic_to_shared(Wq_s) + sub * 40;
    unsigned wk = (unsigned)__cvta_generic_to_shared(Wk_s) + sub * 40;
    unsigned wv = (unsigned)__cvta_generic_to_shared(Wv_s) + sub * 40;
    u64 aq[5], ak[5], av[5];
    #pragma unroll
    for (int p = 0; p < 5; p++) { aq[p] = 0; ak[p] = 0; av[p] = 0; }
    #pragma unroll 4
    for (int k = 0; k < DD; k++) {
        u64 hk = pack2(xa[k], xa[k]);
        unsigned off = k * (DD*4);
        #pragma unroll
        for (int p = 0; p < 5; p++) {
            aq[p] = ffma2(hk, lds1(wq + off + p*8), aq[p]);
            ak[p] = ffma2(hk, lds1(wk + off + p*8), ak[p]);
            av[p] = ffma2(hk, lds1(wv + off + p*8), av[p]);
        }
    }
    float* qp = g_q + row * DD + sub * 10;
    float* kp = g_k + row * DD + sub * 10;
    float* vp = g_v + row * DD + sub * 10;
    #pragma unroll
    for (int p = 0; p < 5; p++) {
        *(float2*)(qp + 2*p) = unpack2(aq[p]);
        *(float2*)(kp + 2*p) = unpack2(ak[p]);
        *(float2*)(vp + 2*p) = unpack2(av[p]);
    }
}

// ---------- attention: full-dim flash, 1 query/thread, split-K x8 ----------
// grid (16, 8, 8), 128 threads.
__global__ __launch_bounds__(128, 4) void attn_kernel(const float* __restrict__ rel_bias)
{
    __shared__ __align__(16) float bias_s[KEYS_PER + 128];
    __shared__ __align__(16) float Ks[TKA*DD];
    __shared__ __align__(16) float Vs[TKA*DD];

    int tid = threadIdx.x;
    int b = blockIdx.y, z = blockIdx.z;
    int q0 = blockIdx.x * 128;
    int qi = q0 + tid;
    size_t row = (size_t)b * SS + qi;
    const float LOG2E = 1.4426950408889634f;

    int rel0 = z * KEYS_PER - q0 - 127;
    for (int i = tid; i < KEYS_PER + 128; i += 128)
        bias_s[i] = rel_bias[rel_bucket(rel0 + i)] * LOG2E;

    u64 q2[DP];
    {
        const u64* qp = (const u64*)(g_q + row * DD);
        #pragma unroll
        for (int d = 0; d < DP; d++) q2[d] = qp[d];
    }
    u64 o2[DP];
    #pragma unroll
    for (int d = 0; d < DP; d++) o2[d] = 0ull;
    float m = -INFINITY, l = 0.f;

    const float* kbase = g_k + ((size_t)b * SS + z * KEYS_PER) * DD;
    const float* vbase = g_v + ((size_t)b * SS + z * KEYS_PER) * DD;
    unsigned ks_base = (unsigned)__cvta_generic_to_shared(Ks);
    unsigned vs_base = (unsigned)__cvta_generic_to_shared(Vs);
    int base_off = 127 - tid;
    __syncthreads();

    #pragma unroll 1
    for (int t = 0; t < KEYS_PER / TKA; t++) {
        {
            const float4* ksrc = (const float4*)(kbase + t * TKA * DD);
            const float4* vsrc = (const float4*)(vbase + t * TKA * DD);
            float4* kd = (float4*)Ks; float4* vd = (float4*)Vs;
            #pragma unroll
            for (int i = tid; i < TKA*DD/4; i += 128) { kd[i] = ksrc[i]; vd[i] = vsrc[i]; }
        }
        __syncthreads();

        int boff = t * TKA + base_off;
        #pragma unroll 1
        for (int c = 0; c < TKA/4; c++) {
            int k0 = c * 4;
            float s[4];
            #pragma unroll
            for (int kk = 0; kk < 4; kk++) {
                unsigned ka = ks_base + (k0 + kk) * (DD*4);
                u64 a0 = 0, a1 = 0;
                #pragma unroll
                for (int d = 0; d < 10; d++) {
                    u64 ua, ub;
                    lds2(ua, ub, ka + d * 16);
                    a0 = ffma2(q2[2*d],   ua, a0);
                    a1 = ffma2(q2[2*d+1], ub, a1);
                }
                float2 f = unpack2(fadd2(a0, a1));
                s[kk] = fmaf(f.x + f.y, LOG2E, bias_s[boff + k0 + kk]);
            }
            float tmax = fmaxf(fmaxf(s[0], s[1]), fmaxf(s[2], s[3]));
            if (tmax > m) {
                float corr = exp2f(m - tmax);
                l *= corr;
                u64 c2 = pack2(corr, corr);
                #pragma unroll
                for (int d = 0; d < DP; d++) o2[d] = fmul2(o2[d], c2);
                m = tmax;
            }
            #pragma unroll
            for (int kk = 0; kk < 4; kk++) {
                float p = exp2f(s[kk] - m);
                l += p;
                u64 p2 = pack2(p, p);
                unsigned va = vs_base + (k0 + kk) * (DD*4);
                #pragma unroll
                for (int d = 0; d < 10; d++) {
                    u64 ua, ub;
                    lds2(ua, ub, va + d * 16);
                    o2[2*d]   = ffma2(p2, ua, o2[2*d]);
                    o2[2*d+1] = ffma2(p2, ub, o2[2*d+1]);
                }
            }
        }
        __syncthreads();
    }

    size_t pidx = (size_t)z * NROWS + row;
    g_pm[pidx] = m;
    g_pl[pidx] = l;
    float2* pop = (float2*)(g_po + pidx * DD);
    #pragma unroll
    for (int d = 0; d < DP; d++) pop[d] = unpack2(o2[d]);
}

// ---------- combine partials + fused epilogue ----------
__global__ __launch_bounds__(128) void combine_kernel(
    const float* __restrict__ Wo, const float* __restrict__ ln2,
    const float* __restrict__ wi, const float* __restrict__ wo,
    const float* __restrict__ lnf, float* __restrict__ out)
{
    __shared__ __align__(16) float Wo_s[DD*DD], wi_s[DD*DD], wo_s[DD*DD];
    __shared__ __align__(16) float ln2_s[DD], lnf_s[DD];
    int tid = threadIdx.x;
    for (int i = tid; i < DD*DD; i += 128) { Wo_s[i] = Wo[i]; wi_s[i] = wi[i]; wo_s[i] = wo[i]; }
    if (tid < DD) { ln2_s[tid] = ln2[tid]; lnf_s[tid] = lnf[tid]; }
    __syncthreads();

    size_t row = (size_t)blockIdx.x * 128 + tid;

    float M = -INFINITY;
    float mz[RSPLIT], lz[RSPLIT];
    #pragma unroll
    for (int z = 0; z < RSPLIT; z++) {
        mz[z] = g_pm[(size_t)z * NROWS + row];
        lz[z] = g_pl[(size_t)z * NROWS + row];
        M = fmaxf(M, mz[z]);
    }
    float L = 0.f;
    float oarr[DD];
    #pragma unroll
    for (int d = 0; d < DD; d++) oarr[d] = 0.f;
    #pragma unroll
    for (int z = 0; z < RSPLIT; z++) {
        float wz = exp2f(mz[z] - M);
        L = fmaf(wz, lz[z], L);
        const float4* pp = (const float4*)(g_po + ((size_t)z * NROWS + row) * DD);
        #pragma unroll
        for (int d = 0; d < 10; d++) {
            float4 v = pp[d];
            oarr[4*d]   = fmaf(wz, v.x, oarr[4*d]);
            oarr[4*d+1] = fmaf(wz, v.y, oarr[4*d+1]);
            oarr[4*d+2] = fmaf(wz, v.z, oarr[4*d+2]);
            oarr[4*d+3] = fmaf(wz, v.w, oarr[4*d+3]);
        }
    }
    float invl = 1.0f / L;
    #pragma unroll
    for (int d = 0; d < DD; d++) oarr[d] *= invl;

    u64 acc[DP];
    #pragma unroll
    for (int d = 0; d < DP; d++) acc[d] = 0ull;
    const u64* Wo2 = (const u64*)Wo_s;
    #pragma unroll 8
    for (int k = 0; k < DD; k++) {
        u64 ok = pack2(oarr[k], oarr[k]);
        #pragma unroll
        for (int d = 0; d < DP; d++) acc[d] = ffma2(ok, Wo2[k*DP + d], acc[d]);
    }
    float x2a[DD]; float ssq = 0.f;
    {
        const u64* xp = (const u64*)(g_x + row * DD);
        #pragma unroll
        for (int d = 0; d < DP; d++) {
            float2 xv = unpack2(xp[d]); float2 ov = unpack2(acc[d]);
            float a0 = xv.x + ov.x, a1 = xv.y + ov.y;
            x2a[2*d] = a0; x2a[2*d+1] = a1;
            ssq += a0*a0 + a1*a1;
        }
    }
    float r2 = rsqrtf(ssq / 40.0f + 1e-6f);
    float h2a[DD];
    #pragma unroll
    for (int d = 0; d < DD; d++) h2a[d] = x2a[d] * r2 * ln2_s[d];
    u64 acc2[DP];
    #pragma unroll
    for (int d = 0; d < DP; d++) acc2[d] = 0ull;
    const u64* wi2 = (const u64*)wi_s;
    #pragma unroll 8
    for (int k = 0; k < DD; k++) {
        u64 hk = pack2(h2a[k], h2a[k]);
        #pragma unroll
        for (int d = 0; d < DP; d++) acc2[d] = ffma2(hk, wi2[k*DP + d], acc2[d]);
    }
    float f1[DD];
    #pragma unroll
    for (int d = 0; d < DP; d++) {
        float2 f = unpack2(acc2[d]);
        f1[2*d] = fmaxf(f.x, 0.f); f1[2*d+1] = fmaxf(f.y, 0.f);
    }
    u64 acc3[DP];
    #pragma unroll
    for (int d = 0; d < DP; d++) acc3[d] = 0ull;
    const u64* wo2 = (const u64*)wo_s;
    #pragma unroll 8
    for (int k = 0; k < DD; k++) {
        u64 fk = pack2(f1[k], f1[k]);
        #pragma unroll
        for (int d = 0; d < DP; d++) acc3[d] = ffma2(fk, wo2[k*DP + d], acc3[d]);
    }
    float x3[DD]; float ssq3 = 0.f;
    #pragma unroll
    for (int d = 0; d < DP; d++) {
        float2 fv = unpack2(acc3[d]);
        float a0 = x2a[2*d] + fv.x, a1 = x2a[2*d+1] + fv.y;
        x3[2*d] = a0; x3[2*d+1] = a1;
        ssq3 += a0*a0 + a1*a1;
    }
    float r3 = rsqrtf(ssq3 / 40.0f + 1e-6f);
    float* orow = out + row * DD;
    #pragma unroll
    for (int d = 0; d < DP; d++) {
        *(float2*)(orow + 2*d) = make_float2(x3[2*d]   * r3 * lnf_s[2*d],
                                             x3[2*d+1] * r3 * lnf_s[2*d+1]);
    }
}

// ---------- launch ----------
extern "C" void kernel_launch(void* const* d_in, const int* in_sizes, int n_in,
                              void* d_out, int out_size) {
    const float* embs = (const float*)d_in[0];
    const float* Wa   = (const float*)d_in[1];
    const float* ba   = (const float*)d_in[2];
    const float* ln1  = (const float*)d_in[3];
    const float* Wq   = (const float*)d_in[4];
    const float* Wk   = (const float*)d_in[5];
    const float* Wv   = (const float*)d_in[6];
    const float* Wo   = (const float*)d_in[7];
    const float* ln2  = (const float*)d_in[8];
    const float* wi   = (const float*)d_in[9];
    const float* wo   = (const float*)d_in[10];
    const float* lnf  = (const float*)d_in[11];
    const float* rel_bias = (const float*)d_in[12];
    float* out = (float*)d_out;

    kernelA<<<NROWS/64, 256>>>(embs, Wa, ba, ln1, Wq, Wk, Wv);
    dim3 gridB(SS / 128, BB, RSPLIT);
    attn_kernel<<<gridB, 128>>>(rel_bias);
    combine_kernel<<<NROWS/128, 128>>>(Wo, ln2, wi, wo, lnf, out);
}

// round 17
// speedup vs baseline: 2.8864x; 2.8864x over previous
#include <cuda_runtime.h>
#include <cuda_bf16.h>
#include <math.h>

typedef unsigned long long u64;
typedef unsigned int u32;

#define BB 8
#define SS 2048
#define DIN 128
#define DD 40
#define NROWS (BB*SS)
#define QT 64          // queries per attn CTA
#define TKA 64         // keys per tile
#define NT (SS/TKA)    // 32 tiles

// ---------- scratch ----------
__device__ float g_x[NROWS*DD];
__device__ __nv_bfloat16 g_qh[NROWS*DD];   // q * LOG2E, bf16
__device__ __nv_bfloat16 g_kh[NROWS*DD];
__device__ __nv_bfloat16 g_vh[NROWS*DD];

// ---------- helpers ----------
__device__ __forceinline__ u64 pack2(float x, float y) {
    u64 r; asm("mov.b64 %0,{%1,%2};" : "=l"(r) : "f"(x), "f"(y)); return r;
}
__device__ __forceinline__ float2 unpack2(u64 a) {
    float x, y; asm("mov.b64 {%0,%1},%2;" : "=f"(x), "=f"(y) : "l"(a));
    return make_float2(x, y);
}
__device__ __forceinline__ u64 ffma2(u64 a, u64 b, u64 c) {
    u64 d; asm("fma.rn.f32x2 %0,%1,%2,%3;" : "=l"(d) : "l"(a), "l"(b), "l"(c)); return d;
}
__device__ __forceinline__ void lds2(u64& a, u64& b, unsigned addr) {
    asm("ld.shared.v2.b64 {%0,%1},[%2];" : "=l"(a), "=l"(b) : "r"(addr));
}
__device__ __forceinline__ u32 cvtbf2(float hi, float lo) {
    u32 r; asm("cvt.rn.bf16x2.f32 %0,%1,%2;" : "=r"(r) : "f"(hi), "f"(lo)); return r;
}
__device__ __forceinline__ float ex2f(float x) {
    float r; asm("ex2.approx.f32 %0,%1;" : "=f"(r) : "f"(x)); return r;
}
__device__ __forceinline__ void mma16816(float* d, u32 a0, u32 a1, u32 a2, u32 a3, u32 b0, u32 b1) {
    asm("mma.sync.aligned.m16n8k16.row.col.f32.bf16.bf16.f32 "
        "{%0,%1,%2,%3},{%4,%5,%6,%7},{%8,%9},{%0,%1,%2,%3};"
        : "+f"(d[0]), "+f"(d[1]), "+f"(d[2]), "+f"(d[3])
        : "r"(a0), "r"(a1), "r"(a2), "r"(a3), "r"(b0), "r"(b1));
}
__device__ __forceinline__ void mma1688(float* d, u32 a0, u32 a1, u32 b0) {
    asm("mma.sync.aligned.m16n8k8.row.col.f32.bf16.bf16.f32 "
        "{%0,%1,%2,%3},{%4,%5},{%6},{%0,%1,%2,%3};"
        : "+f"(d[0]), "+f"(d[1]), "+f"(d[2]), "+f"(d[3])
        : "r"(a0), "r"(a1), "r"(b0));
}

__device__ __forceinline__ int rel_bucket(int rel) {
    int bucket = (rel > 0) ? 16 : 0;
    int a = rel < 0 ? -rel : rel;
    if (a < 8) return bucket + a;
    float v = (logf((float)a * 0.125f) / 2.7725887222397811f) * 8.0f;
    int large = 8 + (int)v;
    return bucket + ((large < 15) ? large : 15);
}

#define LOG2E 1.4426950408889634f

// ---------- kernel A: col-split (2 thr/row): adapter+rms+QKV, bf16 out ----------
__global__ __launch_bounds__(128, 4) void kernelA(
    const float* __restrict__ embs, const float* __restrict__ Wa,
    const float* __restrict__ ba,   const float* __restrict__ ln1,
    const float* __restrict__ Wq,   const float* __restrict__ Wk,
    const float* __restrict__ Wv)
{
    __shared__ __align__(16) float Wa_s[DIN*DD];
    __shared__ __align__(16) float Wq_s[DD*DD], Wk_s[DD*DD], Wv_s[DD*DD];
    __shared__ __align__(16) float ba_s[DD], ln1_s[DD];

    int tid = threadIdx.x;
    for (int i = tid; i < DIN*DD/4; i += 128) ((float4*)Wa_s)[i] = ((const float4*)Wa)[i];
    for (int i = tid; i < DD*DD; i += 128) {
        Wq_s[i] = Wq[i] * LOG2E;   // fold LOG2E into q
        Wk_s[i] = Wk[i];
        Wv_s[i] = Wv[i];
    }
    if (tid < DD) { ba_s[tid] = ba[tid]; ln1_s[tid] = ln1[tid]; }
    __syncthreads();

    int half = tid & 1;
    int hc = half * 20;                       // this thread's column base
    size_t row = (size_t)blockIdx.x * 64 + (tid >> 1);

    // adapter partial: all 128 k, 20 output cols
    u64 acc[10];
    #pragma unroll
    for (int p = 0; p < 10; p++) acc[p] = 0ull;
    const float4* erow = (const float4*)(embs + row * DIN);
    unsigned wa = (unsigned)__cvta_generic_to_shared(Wa_s) + half * 80;
    #pragma unroll 4
    for (int c = 0; c < 32; c++) {
        float4 e = erow[c];
        float ej[4] = {e.x, e.y, e.z, e.w};
        #pragma unroll
        for (int j = 0; j < 4; j++) {
            u64 ee = pack2(ej[j], ej[j]);
            unsigned a = wa + (4*c + j) * (DD*4);
            #pragma unroll
            for (int p = 0; p < 5; p++) {
                u64 ua, ub;
                lds2(ua, ub, a + p * 16);
                acc[2*p]   = ffma2(ee, ua, acc[2*p]);
                acc[2*p+1] = ffma2(ee, ub, acc[2*p+1]);
            }
        }
    }

    // + bias, relu, store x, rms
    float xa[20]; float ssq = 0.f;
    #pragma unroll
    for (int p = 0; p < 10; p++) {
        float2 f = unpack2(acc[p]);
        float x0 = fmaxf(f.x + ba_s[hc + 2*p], 0.f);
        float x1 = fmaxf(f.y + ba_s[hc + 2*p + 1], 0.f);
        xa[2*p] = x0; xa[2*p+1] = x1;
        ssq += x0*x0 + x1*x1;
    }
    {
        float* xp = g_x + row * DD + hc;
        #pragma unroll
        for (int p = 0; p < 10; p++) *(float2*)(xp + 2*p) = make_float2(xa[2*p], xa[2*p+1]);
    }
    ssq += __shfl_xor_sync(0xffffffffu, ssq, 1);
    float rinv = rsqrtf(ssq / 40.0f + 1e-6f);

    // full h: own 20 + partner's 20 via shfl
    float h[DD];
    #pragma unroll
    for (int j = 0; j < 20; j++) h[hc + j] = xa[j] * rinv * ln1_s[hc + j];
    int oc = 20 - hc;   // other column base
    #pragma unroll
    for (int j = 0; j < 20; j++) {
        float o = __shfl_xor_sync(0xffffffffu, xa[j], 1);
        h[oc + j] = o * rinv * ln1_s[oc + j];
    }

    // QKV: 20 cols of each
    unsigned wq = (unsigned)__cvta_generic_to_shared(Wq_s) + half * 80;
    unsigned wk = (unsigned)__cvta_generic_to_shared(Wk_s) + half * 80;
    unsigned wv = (unsigned)__cvta_generic_to_shared(Wv_s) + half * 80;
    u64 aq[10], ak[10], av[10];
    #pragma unroll
    for (int p = 0; p < 10; p++) { aq[p] = 0; ak[p] = 0; av[p] = 0; }
    #pragma unroll 4
    for (int k = 0; k < DD; k++) {
        u64 hk = pack2(h[k], h[k]);
        unsigned off = k * (DD*4);
        u64 ua, ub;
        #pragma unroll
        for (int p = 0; p < 5; p++) {
            lds2(ua, ub, wq + off + p*16);
            aq[2*p] = ffma2(hk, ua, aq[2*p]); aq[2*p+1] = ffma2(hk, ub, aq[2*p+1]);
        }
        #pragma unroll
        for (int p = 0; p < 5; p++) {
            lds2(ua, ub, wk + off + p*16);
            ak[2*p] = ffma2(hk, ua, ak[2*p]); ak[2*p+1] = ffma2(hk, ub, ak[2*p+1]);
        }
        #pragma unroll
        for (int p = 0; p < 5; p++) {
            lds2(ua, ub, wv + off + p*16);
            av[2*p] = ffma2(hk, ua, av[2*p]); av[2*p+1] = ffma2(hk, ub, av[2*p+1]);
        }
    }
    // bf16 stores
    u32* qp = (u32*)(g_qh + row * DD) + half * 10;
    u32* kp = (u32*)(g_kh + row * DD) + half * 10;
    u32* vp = (u32*)(g_vh + row * DD) + half * 10;
    #pragma unroll
    for (int p = 0; p < 10; p++) {
        float2 fq = unpack2(aq[p]); qp[p] = cvtbf2(fq.y, fq.x);
        float2 fk = unpack2(ak[p]); kp[p] = cvtbf2(fk.y, fk.x);
        float2 fv = unpack2(av[p]); vp[p] = cvtbf2(fv.y, fv.x);
    }
}

// ---------- attention: FA2 mma.sync bf16 + fused epilogue ----------
// smem layout offsets (bytes)
#define SM_BIAS 0                 // 2112 f32 = 8448
#define SM_KS   8448              // 64x40 bf16 = 5120
#define SM_VT   13568             // 40x72 bf16 = 5760
#define SM_OS   8448              // alias over KS+VT: 64x40 f32 = 10240
#define SM_WO   19328             // 1600 f32
#define SM_WI   25728
#define SM_WO2  32128
#define SM_LN2  38528             // 40 f32
#define SM_LNF  38688             // 40 f32
#define SM_TOT  38848

__global__ __launch_bounds__(128, 4) void attn_kernel(
    const float* __restrict__ rel_bias,
    const float* __restrict__ Wo, const float* __restrict__ ln2,
    const float* __restrict__ wi, const float* __restrict__ wo,
    const float* __restrict__ lnf, float* __restrict__ out)
{
    __shared__ __align__(16) char sm[SM_TOT];
    float* bias_s = (float*)(sm + SM_BIAS);
    float* Wo_s = (float*)(sm + SM_WO);
    float* wi_s = (float*)(sm + SM_WI);
    float* wo_s = (float*)(sm + SM_WO2);
    float* ln2_s = (float*)(sm + SM_LN2);
    float* lnf_s = (float*)(sm + SM_LNF);

    int tid = threadIdx.x;
    int w = tid >> 5, lane = tid & 31;
    int qg = lane >> 2, tg = lane & 3;
    int b = blockIdx.y;
    int q0 = blockIdx.x * QT;

    // preamble: bias window + epilogue weights
    for (int i = tid; i < SS + QT; i += 128)
        bias_s[i] = rel_bias[rel_bucket(i - (QT-1) - q0)] * LOG2E;
    for (int i = tid; i < DD*DD; i += 128) { Wo_s[i] = Wo[i]; wi_s[i] = wi[i]; wo_s[i] = wo[i]; }
    if (tid < DD) { ln2_s[tid] = ln2[tid]; lnf_s[tid] = lnf[tid]; }

    // Q fragments (bf16x2), rows row0 / row0+8
    int row0 = q0 + w*16 + qg;
    const u32* qgp = (const u32*)(g_qh + ((size_t)b * SS + row0) * DD);
    const u32* qgp8 = (const u32*)(g_qh + ((size_t)b * SS + row0 + 8) * DD);
    u32 qa[2][4], qa2[2];
    #pragma unroll
    for (int c = 0; c < 2; c++) {
        qa[c][0] = qgp [8*c + tg];        // d = 16c + 2tg
        qa[c][1] = qgp8[8*c + tg];
        qa[c][2] = qgp [8*c + tg + 4];    // d + 8
        qa[c][3] = qgp8[8*c + tg + 4];
    }
    qa2[0] = qgp[16 + tg];                // d = 32 + 2tg
    qa2[1] = qgp8[16 + tg];

    float o[5][4];
    #pragma unroll
    for (int nd = 0; nd < 5; nd++)
        #pragma unroll
        for (int j = 0; j < 4; j++) o[nd][j] = 0.f;
    float m0 = -INFINITY, m1 = -INFINITY, l0 = 0.f, l1 = 0.f;

    const u32* Kg = (const u32*)(g_kh + (size_t)b * SS * DD);
    const u32* Vg = (const u32*)(g_vh + (size_t)b * SS * DD);
    u32* Ks32 = (u32*)(sm + SM_KS);
    const char* KSp = sm + SM_KS;
    const char* VTp = sm + SM_VT;

    int ibase0 = (QT-1) - w*16 - qg;      // bias idx base for row0

    // prefetch tile 0
    u32 kpre[10], vpre[10];
    #pragma unroll
    for (int i = 0; i < 10; i++) {
        kpre[i] = Kg[tid + i*128];
        vpre[i] = Vg[tid + i*128];
    }
    __syncthreads();   // bias/weights ready

    #pragma unroll 1
    for (int t = 0; t < NT; t++) {
        // store staged tile
        #pragma unroll
        for (int i = 0; i < 10; i++) Ks32[tid + i*128] = kpre[i];
        #pragma unroll
        for (int i = 0; i < 10; i++) {
            int idx = tid + i*128;
            int key = idx / 20, p = idx % 20;
            u32 v = vpre[i];
            *(unsigned short*)(VTp + ((2*p)*72 + key)*2)   = (unsigned short)(v & 0xffff);
            *(unsigned short*)(VTp + ((2*p+1)*72 + key)*2) = (unsigned short)(v >> 16);
        }
        __syncthreads();
        if (t + 1 < NT) {
            const u32* Kn = Kg + (t+1) * (TKA*20);
            const u32* Vn = Vg + (t+1) * (TKA*20);
            #pragma unroll
            for (int i = 0; i < 10; i++) { kpre[i] = Kn[tid + i*128]; vpre[i] = Vn[tid + i*128]; }
        }

        // ---- QK: S[16 q][64 keys] ----
        float s[8][4];
        #pragma unroll
        for (int n = 0; n < 8; n++) {
            #pragma unroll
            for (int j = 0; j < 4; j++) s[n][j] = 0.f;
            unsigned kb = ((n*8 + qg) * 40 + 2*tg) * 2;
            u32 b00 = *(const u32*)(KSp + kb);
            u32 b01 = *(const u32*)(KSp + kb + 16);
            mma16816(s[n], qa[0][0], qa[0][1], qa[0][2], qa[0][3], b00, b01);
            u32 b10 = *(const u32*)(KSp + kb + 32);
            u32 b11 = *(const u32*)(KSp + kb + 48);
            mma16816(s[n], qa[1][0], qa[1][1], qa[1][2], qa[1][3], b10, b11);
            u32 b20 = *(const u32*)(KSp + kb + 64);
            mma1688(s[n], qa2[0], qa2[1], b20);
        }
        // ---- + bias ----
        int ib = t*TKA + ibase0 + 2*tg;
        #pragma unroll
        for (int n = 0; n < 8; n++) {
            s[n][0] += bias_s[ib + n*8];
            s[n][1] += bias_s[ib + n*8 + 1];
            s[n][2] += bias_s[ib + n*8 - 8];
            s[n][3] += bias_s[ib + n*8 - 7];
        }
        // ---- online softmax ----
        float mx0 = s[0][0], mx1 = s[0][2];
        #pragma unroll
        for (int n = 0; n < 8; n++) {
            mx0 = fmaxf(mx0, fmaxf(s[n][0], s[n][1]));
            mx1 = fmaxf(mx1, fmaxf(s[n][2], s[n][3]));
        }
        mx0 = fmaxf(mx0, __shfl_xor_sync(0xffffffffu, mx0, 1));
        mx0 = fmaxf(mx0, __shfl_xor_sync(0xffffffffu, mx0, 2));
        mx1 = fmaxf(mx1, __shfl_xor_sync(0xffffffffu, mx1, 1));
        mx1 = fmaxf(mx1, __shfl_xor_sync(0xffffffffu, mx1, 2));
        float nm0 = fmaxf(m0, mx0), nm1 = fmaxf(m1, mx1);
        float c0 = ex2f(m0 - nm0), c1 = ex2f(m1 - nm1);
        m0 = nm0; m1 = nm1;
        float ls0 = 0.f, ls1 = 0.f;
        #pragma unroll
        for (int n = 0; n < 8; n++) {
            s[n][0] = ex2f(s[n][0] - m0); ls0 += s[n][0];
            s[n][1] = ex2f(s[n][1] - m0); ls0 += s[n][1];
            s[n][2] = ex2f(s[n][2] - m1); ls1 += s[n][2];
            s[n][3] = ex2f(s[n][3] - m1); ls1 += s[n][3];
        }
        l0 = l0 * c0 + ls0;
        l1 = l1 * c1 + ls1;
        #pragma unroll
        for (int nd = 0; nd < 5; nd++) {
            o[nd][0] *= c0; o[nd][1] *= c0;
            o[nd][2] *= c1; o[nd][3] *= c1;
        }
        // ---- PV ----
        #pragma unroll
        for (int c = 0; c < 4; c++) {
            u32 pa0 = cvtbf2(s[2*c][1],   s[2*c][0]);
            u32 pa1 = cvtbf2(s[2*c][3],   s[2*c][2]);
            u32 pa2 = cvtbf2(s[2*c+1][1], s[2*c+1][0]);
            u32 pa3 = cvtbf2(s[2*c+1][3], s[2*c+1][2]);
            #pragma unroll
            for (int nd = 0; nd < 5; nd++) {
                unsigned vb = ((nd*8 + qg) * 72 + 16*c + 2*tg) * 2;
                u32 b0 = *(const u32*)(VTp + vb);
                u32 b1 = *(const u32*)(VTp + vb + 16);
                mma16816(o[nd], pa0, pa1, pa2, pa3, b0, b1);
            }
        }
        __syncthreads();
    }

    // finalize l, normalize, write O_s
    l0 += __shfl_xor_sync(0xffffffffu, l0, 1);
    l0 += __shfl_xor_sync(0xffffffffu, l0, 2);
    l1 += __shfl_xor_sync(0xffffffffu, l1, 1);
    l1 += __shfl_xor_sync(0xffffffffu, l1, 2);
    float inv0 = 1.0f / l0, inv1 = 1.0f / l1;

    float* OS = (float*)(sm + SM_OS);
    int ql0 = w*16 + qg;
    __syncthreads();   // all warps done with Ks/Vt before alias write
    #pragma unroll
    for (int nd = 0; nd < 5; nd++) {
        OS[ql0*40 + nd*8 + 2*tg]       = o[nd][0] * inv0;
        OS[ql0*40 + nd*8 + 2*tg + 1]   = o[nd][1] * inv0;
        OS[(ql0+8)*40 + nd*8 + 2*tg]     = o[nd][2] * inv1;
        OS[(ql0+8)*40 + nd*8 + 2*tg + 1] = o[nd][3] * inv1;
    }
    __syncthreads();

    // ---- fused epilogue: threads 0..63, one row each ----
    if (tid < QT) {
        size_t row = (size_t)b * SS + q0 + tid;
        float oarr[DD];
        #pragma unroll
        for (int k = 0; k < DD; k++) oarr[k] = OS[tid*40 + k];

        u64 acc[20];
        #pragma unroll
        for (int d = 0; d < 20; d++) acc[d] = 0ull;
        const u64* Wo2 = (const u64*)Wo_s;
        #pragma unroll 8
        for (int k = 0; k < DD; k++) {
            u64 ok = pack2(oarr[k], oarr[k]);
            #pragma unroll
            for (int d = 0; d < 20; d++) acc[d] = ffma2(ok, Wo2[k*20 + d], acc[d]);
        }
        float x2a[DD]; float ssq = 0.f;
        const u64* xp = (const u64*)(g_x + row * DD);
        #pragma unroll
        for (int d = 0; d < 20; d++) {
            float2 xv = unpack2(xp[d]); float2 ov = unpack2(acc[d]);
            float a0 = xv.x + ov.x, a1 = xv.y + ov.y;
            x2a[2*d] = a0; x2a[2*d+1] = a1;
            ssq += a0*a0 + a1*a1;
        }
        float r2 = rsqrtf(ssq / 40.0f + 1e-6f);
        float h2a[DD];
        #pragma unroll
        for (int d = 0; d < DD; d++) h2a[d] = x2a[d] * r2 * ln2_s[d];
        u64 acc2[20];
        #pragma unroll
        for (int d = 0; d < 20; d++) acc2[d] = 0ull;
        const u64* wi2 = (const u64*)wi_s;
        #pragma unroll 8
        for (int k = 0; k < DD; k++) {
            u64 hk = pack2(h2a[k], h2a[k]);
            #pragma unroll
            for (int d = 0; d < 20; d++) acc2[d] = ffma2(hk, wi2[k*20 + d], acc2[d]);
        }
        float f1[DD];
        #pragma unroll
        for (int d = 0; d < 20; d++) {
            float2 f = unpack2(acc2[d]);
            f1[2*d] = fmaxf(f.x, 0.f); f1[2*d+1] = fmaxf(f.y, 0.f);
        }
        u64 acc3[20];
        #pragma unroll
        for (int d = 0; d < 20; d++) acc3[d] = 0ull;
        const u64* wo2 = (const u64*)wo_s;
        #pragma unroll 8
        for (int k = 0; k < DD; k++) {
            u64 fk = pack2(f1[k], f1[k]);
            #pragma unroll
            for (int d = 0; d < 20; d++) acc3[d] = ffma2(fk, wo2[k*20 + d], acc3[d]);
        }
        float x3[DD]; float ssq3 = 0.f;
        #pragma unroll
        for (int d = 0; d < 20; d++) {
            float2 fv = unpack2(acc3[d]);
            float a0 = x2a[2*d] + fv.x, a1 = x2a[2*d+1] + fv.y;
            x3[2*d] = a0; x3[2*d+1] = a1;
            ssq3 += a0*a0 + a1*a1;
        }
        float r3 = rsqrtf(ssq3 / 40.0f + 1e-6f);
        float* orow = out + row * DD;
        #pragma unroll
        for (int d = 0; d < 20; d++) {
            *(float2*)(orow + 2*d) = make_float2(x3[2*d]   * r3 * lnf_s[2*d],
                                                 x3[2*d+1] * r3 * lnf_s[2*d+1]);
        }
    }
}

// ---------- launch ----------
extern "C" void kernel_launch(void* const* d_in, const int* in_sizes, int n_in,
                              void* d_out, int out_size) {
    const float* embs = (const float*)d_in[0];
    const float* Wa   = (const float*)d_in[1];
    const float* ba   = (const float*)d_in[2];
    const float* ln1  = (const float*)d_in[3];
    const float* Wq   = (const float*)d_in[4];
    const float* Wk   = (const float*)d_in[5];
    const float* Wv   = (const float*)d_in[6];
    const float* Wo   = (const float*)d_in[7];
    const float* ln2  = (const float*)d_in[8];
    const float* wi   = (const float*)d_in[9];
    const float* wo   = (const float*)d_in[10];
    const float* lnf  = (const float*)d_in[11];
    const float* rel_bias = (const float*)d_in[12];
    float* out = (float*)d_out;

    kernelA<<<NROWS/64, 128>>>(embs, Wa, ba, ln1, Wq, Wk, Wv);
    dim3 gridB(SS / QT, BB);
    attn_kernel<<<gridB, 128>>>(rel_bias, Wo, ln2, wi, wo, lnf, out);
}